// round 4
// baseline (speedup 1.0000x reference)
#include <cuda_runtime.h>

#define NN 40000
#define EE 1280000
#define FF 64
#define HH 64

// Scratch (allocation-free): segment sums
__device__ float g_agg[NN * HH];   // sum of m per node
__device__ float g_aggc[NN * 3];   // sum of trans per node
__device__ float g_cnt[NN];        // edge count per node
__device__ int   g_idx64;          // 1 if edge_index is int64, 0 if int32

__device__ __forceinline__ float silu(float v) {
    return v * (1.0f / (1.0f + __expf(-v)));
}

__global__ void zero_kernel(const int* __restrict__ ei32) {
    int i = blockIdx.x * blockDim.x + threadIdx.x;
    int stride = gridDim.x * blockDim.x;
    for (int k = i; k < NN * HH; k += stride) g_agg[k] = 0.f;
    for (int k = i; k < NN * 3;  k += stride) g_aggc[k] = 0.f;
    for (int k = i; k < NN;      k += stride) g_cnt[k] = 0.f;
    if (i == 0) {
        // int64 little-endian small values => all odd 4-byte words are 0
        int all_zero = 1;
        #pragma unroll
        for (int k = 1; k < 64; k += 2) all_zero &= (ei32[k] == 0);
        g_idx64 = all_zero;
    }
}

// Warp-per-edge: edge MLP + coord MLP + atomics into segment sums.
__global__ void edge_kernel(const float* __restrict__ h, const float* __restrict__ coord,
                            const void* __restrict__ ei_raw, const float* __restrict__ emask,
                            const float* __restrict__ We1, const float* __restrict__ be1,
                            const float* __restrict__ We2, const float* __restrict__ be2,
                            const float* __restrict__ Wc1, const float* __restrict__ bc1,
                            const float* __restrict__ Wc2)
{
    extern __shared__ float sm[];
    float* sW1 = sm;                   // 129*64 = 8256
    float* sW2 = sW1 + 129 * 64;       // 4096
    float* sWc = sW2 + 64 * 64;        // 4096
    float* sc2 = sWc + 64 * 64;        // 64
    float* sb1 = sc2 + 64;             // 64
    float* sb2 = sb1 + 64;             // 64
    float* sbc = sb2 + 64;             // 64
    float* xall = sbc + 64;            // 8 warps * 136

    int tid = threadIdx.x;
    for (int i = tid; i < 129 * 64; i += blockDim.x) sW1[i] = We1[i];
    for (int i = tid; i < 64 * 64; i += blockDim.x) { sW2[i] = We2[i]; sWc[i] = Wc1[i]; }
    if (tid < 64) { sc2[tid] = Wc2[tid]; sb1[tid] = be1[tid]; sb2[tid] = be2[tid]; sbc[tid] = bc1[tid]; }
    __syncthreads();

    const int is64 = g_idx64;
    const long long* ei64 = (const long long*)ei_raw;
    const int*       ei32 = (const int*)ei_raw;

    int lane = tid & 31, warp = tid >> 5;
    float* x = xall + warp * 136;
    const float2* xv = (const float2*)x;
    const float2* W1 = (const float2*)sW1;
    const float2* W2 = (const float2*)sW2;
    const float2* WC = (const float2*)sWc;

    int gw = blockIdx.x * (blockDim.x >> 5) + warp;
    int nw = gridDim.x * (blockDim.x >> 5);

    for (int e = gw; e < EE; e += nw) {
        int r, c;
        if (is64) { r = (int)ei64[e]; c = (int)ei64[EE + e]; }
        else      { r = ei32[e];      c = ei32[EE + e]; }
        // gather inputs: x = [h[r](64), h[c](64), radial(1)], diffs at [129..131]
        x[lane]      = h[(size_t)r * 64 + lane];
        x[32 + lane] = h[(size_t)r * 64 + 32 + lane];
        x[64 + lane] = h[(size_t)c * 64 + lane];
        x[96 + lane] = h[(size_t)c * 64 + 32 + lane];
        if (lane < 3) x[129 + lane] = coord[r * 3 + lane] - coord[c * 3 + lane];
        __syncwarp();
        if (lane == 0) x[128] = x[129] * x[129] + x[130] * x[130] + x[131] * x[131];
        __syncwarp();

        // edge layer 1: [129] -> [64]; lane j computes outputs 2j, 2j+1
        float a0 = sb1[2 * lane], a1 = sb1[2 * lane + 1];
        #pragma unroll 8
        for (int k = 0; k < 64; k++) {
            float2 xk = xv[k];
            float2 w0 = W1[(2 * k) * 32 + lane];
            float2 w1 = W1[(2 * k + 1) * 32 + lane];
            a0 += xk.x * w0.x + xk.y * w1.x;
            a1 += xk.x * w0.y + xk.y * w1.y;
        }
        {
            float xr = x[128];
            float2 w = W1[128 * 32 + lane];
            a0 += xr * w.x; a1 += xr * w.y;
        }
        a0 = silu(a0); a1 = silu(a1);
        __syncwarp();
        x[2 * lane] = a0; x[2 * lane + 1] = a1;
        __syncwarp();

        // edge layer 2: [64] -> [64]
        float b0 = sb2[2 * lane], b1v = sb2[2 * lane + 1];
        #pragma unroll 8
        for (int k = 0; k < 32; k++) {
            float2 xk = xv[k];
            float2 w0 = W2[(2 * k) * 32 + lane];
            float2 w1 = W2[(2 * k + 1) * 32 + lane];
            b0  += xk.x * w0.x + xk.y * w1.x;
            b1v += xk.x * w0.y + xk.y * w1.y;
        }
        float msk = emask[e];
        b0 = silu(b0) * msk;
        b1v = silu(b1v) * msk;
        __syncwarp();
        x[2 * lane] = b0; x[2 * lane + 1] = b1v;
        __syncwarp();

        // aggregate m into g_agg[r] (vector red halves atomic count)
        asm volatile("red.global.add.v2.f32 [%0], {%1, %2};"
                     :: "l"(&g_agg[(size_t)r * 64 + 2 * lane]), "f"(b0), "f"(b1v) : "memory");

        // coord MLP: silu(m@Wc1+bc1) @ Wc2
        float c0 = sbc[2 * lane], c1 = sbc[2 * lane + 1];
        #pragma unroll 8
        for (int k = 0; k < 32; k++) {
            float2 xk = xv[k];
            float2 w0 = WC[(2 * k) * 32 + lane];
            float2 w1 = WC[(2 * k + 1) * 32 + lane];
            c0 += xk.x * w0.x + xk.y * w1.x;
            c1 += xk.x * w0.y + xk.y * w1.y;
        }
        float part = silu(c0) * sc2[2 * lane] + silu(c1) * sc2[2 * lane + 1];
        #pragma unroll
        for (int off = 16; off; off >>= 1)
            part += __shfl_xor_sync(0xffffffffu, part, off);
        float cc = part * msk;  // trans scale (edge_mask applied again per reference)
        if (lane < 3) atomicAdd(&g_aggc[r * 3 + lane], x[129 + lane] * cc);
        if (lane == 0) atomicAdd(&g_cnt[r], 1.0f);
        // shfl above is a full-warp barrier; trailing reads are lane-private
    }
}

// Warp-per-node: node MLP + coord mean epilogue
__global__ void node_kernel(const float* __restrict__ h, const float* __restrict__ coord,
                            const float* __restrict__ Wn1, const float* __restrict__ bn1,
                            const float* __restrict__ Wn2, const float* __restrict__ bn2,
                            float* __restrict__ hout, float* __restrict__ cout)
{
    extern __shared__ float sm[];
    float* sW1 = sm;                  // 128*64 = 8192
    float* sW2 = sW1 + 128 * 64;      // 4096
    float* sb1 = sW2 + 64 * 64;       // 64
    float* sb2 = sb1 + 64;            // 64
    float* xall = sb2 + 64;           // 8 * 128

    int tid = threadIdx.x;
    for (int i = tid; i < 128 * 64; i += blockDim.x) sW1[i] = Wn1[i];
    for (int i = tid; i < 64 * 64; i += blockDim.x) sW2[i] = Wn2[i];
    if (tid < 64) { sb1[tid] = bn1[tid]; sb2[tid] = bn2[tid]; }
    __syncthreads();

    int lane = tid & 31, warp = tid >> 5;
    float* x = xall + warp * 128;
    const float2* xv = (const float2*)x;
    const float2* W1 = (const float2*)sW1;
    const float2* W2 = (const float2*)sW2;

    int gw = blockIdx.x * (blockDim.x >> 5) + warp;
    int nw = gridDim.x * (blockDim.x >> 5);
    for (int n = gw; n < NN; n += nw) {
        x[lane]      = h[(size_t)n * 64 + lane];
        x[32 + lane] = h[(size_t)n * 64 + 32 + lane];
        x[64 + lane] = g_agg[(size_t)n * 64 + lane];
        x[96 + lane] = g_agg[(size_t)n * 64 + 32 + lane];
        __syncwarp();

        float a0 = sb1[2 * lane], a1 = sb1[2 * lane + 1];
        #pragma unroll 8
        for (int k = 0; k < 64; k++) {
            float2 xk = xv[k];
            float2 w0 = W1[(2 * k) * 32 + lane];
            float2 w1 = W1[(2 * k + 1) * 32 + lane];
            a0 += xk.x * w0.x + xk.y * w1.x;
            a1 += xk.x * w0.y + xk.y * w1.y;
        }
        a0 = silu(a0); a1 = silu(a1);
        __syncwarp();
        x[2 * lane] = a0; x[2 * lane + 1] = a1;
        __syncwarp();

        float b0 = sb2[2 * lane], b1v = sb2[2 * lane + 1];
        #pragma unroll 8
        for (int k = 0; k < 32; k++) {
            float2 xk = xv[k];
            float2 w0 = W2[(2 * k) * 32 + lane];
            float2 w1 = W2[(2 * k + 1) * 32 + lane];
            b0  += xk.x * w0.x + xk.y * w1.x;
            b1v += xk.x * w0.y + xk.y * w1.y;
        }
        ((float2*)hout)[n * 32 + lane] = make_float2(b0, b1v);

        if (lane < 3) {
            float cnt = g_cnt[n];
            cnt = cnt > 1.f ? cnt : 1.f;
            cout[n * 3 + lane] = coord[n * 3 + lane] + g_aggc[n * 3 + lane] / cnt;
        }
        __syncwarp();  // protect x across iterations
    }
}

extern "C" void kernel_launch(void* const* d_in, const int* in_sizes, int n_in,
                              void* d_out, int out_size)
{
    const float* h     = (const float*)d_in[0];
    const float* coord = (const float*)d_in[1];
    const void*  ei    = d_in[2];
    const float* emask = (const float*)d_in[3];
    const float* We1 = (const float*)d_in[4];  const float* be1 = (const float*)d_in[5];
    const float* We2 = (const float*)d_in[6];  const float* be2 = (const float*)d_in[7];
    const float* Wn1 = (const float*)d_in[8];  const float* bn1 = (const float*)d_in[9];
    const float* Wn2 = (const float*)d_in[10]; const float* bn2 = (const float*)d_in[11];
    const float* Wc1 = (const float*)d_in[12]; const float* bc1 = (const float*)d_in[13];
    const float* Wc2 = (const float*)d_in[14];

    float* hout = (float*)d_out;
    float* cout = hout + (size_t)NN * FF;

    const int smemE = (129 * 64 + 64 * 64 + 64 * 64 + 64 * 4 + 8 * 136) * 4;  // 71168 B
    const int smemN = (128 * 64 + 64 * 64 + 128 + 8 * 128) * 4;               // 53760 B
    cudaFuncSetAttribute(edge_kernel, cudaFuncAttributeMaxDynamicSharedMemorySize, smemE);
    cudaFuncSetAttribute(node_kernel, cudaFuncAttributeMaxDynamicSharedMemorySize, smemN);

    zero_kernel<<<2048, 256>>>((const int*)ei);
    edge_kernel<<<456, 256, smemE>>>(h, coord, ei, emask,
                                     We1, be1, We2, be2, Wc1, bc1, Wc2);
    node_kernel<<<608, 256, smemN>>>(h, coord, Wn1, bn1, Wn2, bn2, hout, cout);
}

// round 8
// speedup vs baseline: 5.1223x; 5.1223x over previous
#include <cuda_runtime.h>
#include <cuda_bf16.h>
#include <cstdint>

#define NN 40000
#define EE 1280000

// ---------------- scratch (allocation-free) ----------------
__device__ float g_agg[NN * 64];
__device__ float g_aggc[NN * 3];
__device__ float g_cnt[NN];
__device__ float g_H1[NN * 64];   // h @ We1[0:64]  + be1
__device__ float g_H2[NN * 64];   // h @ We1[64:128]
__device__ int   g_idx64;

__device__ __forceinline__ float silu(float v) {
    return v * (1.0f / (1.0f + __expf(-v)));
}

__device__ __forceinline__ uint32_t pack_bf16x2(float lo_elem, float hi_elem) {
    uint32_t r;
    asm("cvt.rn.bf16x2.f32 %0, %1, %2;" : "=r"(r) : "f"(hi_elem), "f"(lo_elem));
    return r;
}
__device__ __forceinline__ void split_pair(float x, float y, uint32_t& hi, uint32_t& lo) {
    hi = pack_bf16x2(x, y);
    __nv_bfloat162 t;
    *reinterpret_cast<uint32_t*>(&t) = hi;
    lo = pack_bf16x2(x - __low2float(t), y - __high2float(t));
}

__device__ __forceinline__ void mma_bf16(float acc[4], uint32_t a0, uint32_t a1,
                                         uint32_t a2, uint32_t a3, uint32_t b0, uint32_t b1) {
    asm volatile(
        "mma.sync.aligned.m16n8k16.row.col.f32.bf16.bf16.f32 "
        "{%0,%1,%2,%3}, {%4,%5,%6,%7}, {%8,%9}, {%0,%1,%2,%3};"
        : "+f"(acc[0]), "+f"(acc[1]), "+f"(acc[2]), "+f"(acc[3])
        : "r"(a0), "r"(a1), "r"(a2), "r"(a3), "r"(b0), "r"(b1));
}

// ---------------- zero + dtype detect ----------------
__global__ void zero_kernel(const int* __restrict__ ei32) {
    int i = blockIdx.x * blockDim.x + threadIdx.x;
    int stride = gridDim.x * blockDim.x;
    for (int k = i; k < NN * 64; k += stride) g_agg[k] = 0.f;
    for (int k = i; k < NN * 3;  k += stride) g_aggc[k] = 0.f;
    for (int k = i; k < NN;      k += stride) g_cnt[k] = 0.f;
    if (i == 0) {
        int all_zero = 1;
        #pragma unroll
        for (int k = 1; k < 64; k += 2) all_zero &= (ei32[k] == 0);
        g_idx64 = all_zero;
    }
}

// ---------------- precompute H1 = h@We1_top + be1, H2 = h@We1_bot ----------------
__global__ void hprep_kernel(const float* __restrict__ h, const float* __restrict__ We1,
                             const float* __restrict__ be1)
{
    extern __shared__ float sm[];
    float* sW = sm;              // We1 rows 0..127 : 8192 floats
    float* sb = sW + 8192;       // 64
    float* xall = sb + 64;       // 8 warps * 64

    int tid = threadIdx.x;
    for (int i = tid; i < 8192; i += blockDim.x) sW[i] = We1[i];
    if (tid < 64) sb[tid] = be1[tid];
    __syncthreads();

    int lane = tid & 31, warp = tid >> 5;
    float* x = xall + warp * 64;
    const float2* xv = (const float2*)x;
    const float2* Wv = (const float2*)sW;   // (k, 2j..2j+1) = Wv[k*32 + j]

    int gw = blockIdx.x * (blockDim.x >> 5) + warp;
    int nw = gridDim.x * (blockDim.x >> 5);
    for (int n = gw; n < NN; n += nw) {
        x[lane]      = h[(size_t)n * 64 + lane];
        x[32 + lane] = h[(size_t)n * 64 + 32 + lane];
        __syncwarp();
        float a0 = 0.f, a1 = 0.f, b0 = 0.f, b1 = 0.f;
        #pragma unroll 8
        for (int k2 = 0; k2 < 32; k2++) {
            float2 xk = xv[k2];
            float2 wA0 = Wv[(2 * k2) * 32 + lane];
            float2 wA1 = Wv[(2 * k2 + 1) * 32 + lane];
            a0 += xk.x * wA0.x + xk.y * wA1.x;
            a1 += xk.x * wA0.y + xk.y * wA1.y;
            float2 wB0 = Wv[(64 + 2 * k2) * 32 + lane];
            float2 wB1 = Wv[(64 + 2 * k2 + 1) * 32 + lane];
            b0 += xk.x * wB0.x + xk.y * wB1.x;
            b1 += xk.x * wB0.y + xk.y * wB1.y;
        }
        ((float2*)g_H1)[(size_t)n * 32 + lane] = make_float2(a0 + sb[2 * lane], a1 + sb[2 * lane + 1]);
        ((float2*)g_H2)[(size_t)n * 32 + lane] = make_float2(b0, b1);
        __syncwarp();
    }
}

// ---------------- edge mega-kernel: warp-per-16-edges, HMMA ----------------
// smem word layout
#define RSTR 36                 // padded row stride in uint32 words (bank-conflict-free)
#define W2H_OFF 0               // 64 rows * 36 = 2304
#define W2L_OFF 2304
#define WCH_OFF 4608
#define BE2_OFF 6912
#define BC1_OFF 6976
#define WC2_OFF 7040
#define W128_OFF 7104
#define PW_OFF  7168
#define PW_SIZE 1808
// per-warp offsets: A2H 0, A2L 576, A3H 1152, MSK 1728, DX 1744, DY 1760, DZ 1776, RIX 1792
#define SM_EDGE_BYTES ((PW_OFF + 16 * PW_SIZE) * 4)   // 144384

__global__ void __launch_bounds__(512, 1)
edge_kernel(const float* __restrict__ coord,
            const void* __restrict__ ei_raw, const float* __restrict__ emask,
            const float* __restrict__ We1, const float* __restrict__ We2,
            const float* __restrict__ be2, const float* __restrict__ Wc1,
            const float* __restrict__ bc1, const float* __restrict__ Wc2)
{
    extern __shared__ uint32_t smw[];
    float* smf = (float*)smw;
    int tid = threadIdx.x;

    // stage weights (transposed to [n][k], padded rows, bf16 hi/lo)
    for (int idx = tid; idx < 4096; idx += 512) {
        int n = idx & 63, k = idx >> 6;
        float v = We2[k * 64 + n];
        __nv_bfloat16 hb = __float2bfloat16(v);
        ((__nv_bfloat16*)(smw + W2H_OFF))[n * 72 + k] = hb;
        ((__nv_bfloat16*)(smw + W2L_OFF))[n * 72 + k] = __float2bfloat16(v - __bfloat162float(hb));
        ((__nv_bfloat16*)(smw + WCH_OFF))[n * 72 + k] = __float2bfloat16(Wc1[k * 64 + n]);
    }
    if (tid < 64) {
        smf[BE2_OFF + tid]  = be2[tid];
        smf[BC1_OFF + tid]  = bc1[tid];
        smf[WC2_OFF + tid]  = Wc2[tid];
        smf[W128_OFF + tid] = We1[128 * 64 + tid];
    }
    __syncthreads();

    const int is64 = g_idx64;
    const long long* ei64 = (const long long*)ei_raw;
    const int*       ei32 = (const int*)ei_raw;

    int lane = tid & 31, warp = tid >> 5;
    uint32_t* pw   = smw + PW_OFF + warp * PW_SIZE;
    uint32_t* A2H  = pw;
    uint32_t* A2L  = pw + 576;
    uint32_t* A3H  = pw + 1152;
    float*    sMSK = (float*)(pw + 1728);
    float*    sDX  = (float*)(pw + 1744);
    float*    sDY  = (float*)(pw + 1760);
    float*    sDZ  = (float*)(pw + 1776);
    int*      sRI  = (int*)(pw + 1792);

    const float* be2s = smf + BE2_OFF;
    const float* bc1s = smf + BC1_OFF;
    const float* wc2s = smf + WC2_OFF;
    const float* w128 = smf + W128_OFF;

    int gw = blockIdx.x * 16 + warp;
    const int r0 = lane >> 2, q = lane & 3;

    for (int g = gw; g < EE / 16; g += 148 * 16) {
        int e0 = g * 16;
        int le = lane >> 1, half = lane & 1;
        int e = e0 + le;
        int ri, ci;
        if (is64) { ri = (int)ei64[e]; ci = (int)ei64[EE + e]; }
        else      { ri = ei32[e];      ci = ei32[EE + e]; }
        float msk = emask[e];
        float dx = coord[ri * 3 + 0] - coord[ci * 3 + 0];
        float dy = coord[ri * 3 + 1] - coord[ci * 3 + 1];
        float dz = coord[ri * 3 + 2] - coord[ci * 3 + 2];
        float radial = dx * dx + dy * dy + dz * dz;
        if (!half) { sMSK[le] = msk; sDX[le] = dx; sDY[le] = dy; sDZ[le] = dz; sRI[le] = ri; }

        // gather + exact layer-1 + silu + bf16 split -> A2
        const float4* p1 = (const float4*)(g_H1 + (size_t)ri * 64 + half * 32);
        const float4* p2 = (const float4*)(g_H2 + (size_t)ci * 64 + half * 32);
        #pragma unroll
        for (int i = 0; i < 8; i++) {
            float4 u = p1[i], v = p2[i];
            int cb = half * 32 + i * 4;
            float x0 = silu(u.x + v.x + radial * w128[cb + 0]);
            float x1 = silu(u.y + v.y + radial * w128[cb + 1]);
            float x2 = silu(u.z + v.z + radial * w128[cb + 2]);
            float x3 = silu(u.w + v.w + radial * w128[cb + 3]);
            uint32_t h0, l0, h1, l1;
            split_pair(x0, x1, h0, l0);
            split_pair(x2, x3, h1, l1);
            int off = le * RSTR + half * 16 + i * 2;
            A2H[off] = h0; A2H[off + 1] = h1;
            A2L[off] = l0; A2L[off + 1] = l1;
        }
        __syncwarp();

        // ---- GEMM2: [16x64] = A2 (3-term bf16) x W2^T ----
        float acc[8][4];
        #pragma unroll
        for (int nt = 0; nt < 8; nt++)
            acc[nt][0] = acc[nt][1] = acc[nt][2] = acc[nt][3] = 0.f;
        #pragma unroll
        for (int ks = 0; ks < 4; ks++) {
            int abase = r0 * RSTR + ks * 8 + q;
            uint32_t ah0 = A2H[abase],            ah1 = A2H[abase + 8 * RSTR];
            uint32_t ah2 = A2H[abase + 4],        ah3 = A2H[abase + 8 * RSTR + 4];
            uint32_t al0 = A2L[abase],            al1 = A2L[abase + 8 * RSTR];
            uint32_t al2 = A2L[abase + 4],        al3 = A2L[abase + 8 * RSTR + 4];
            #pragma unroll
            for (int nt = 0; nt < 8; nt++) {
                int bw = (nt * 8 + r0) * RSTR + ks * 8 + q;
                uint32_t bh0 = smw[W2H_OFF + bw], bh1 = smw[W2H_OFF + bw + 4];
                uint32_t bl0 = smw[W2L_OFF + bw], bl1 = smw[W2L_OFF + bw + 4];
                mma_bf16(acc[nt], ah0, ah1, ah2, ah3, bh0, bh1);
                mma_bf16(acc[nt], al0, al1, al2, al3, bh0, bh1);
                mma_bf16(acc[nt], ah0, ah1, ah2, ah3, bl0, bl1);
            }
        }

        // ---- epilogue2: m = silu(+be2)*mask; red to g_agg; m(hi) -> A3 ----
        float mk0 = sMSK[r0], mk1 = sMSK[r0 + 8];
        int   rn0 = sRI[r0],  rn1 = sRI[r0 + 8];
        #pragma unroll
        for (int nt = 0; nt < 8; nt++) {
            int col = nt * 8 + 2 * q;
            float m00 = silu(acc[nt][0] + be2s[col])     * mk0;
            float m01 = silu(acc[nt][1] + be2s[col + 1]) * mk0;
            float m10 = silu(acc[nt][2] + be2s[col])     * mk1;
            float m11 = silu(acc[nt][3] + be2s[col + 1]) * mk1;
            asm volatile("red.global.add.v2.f32 [%0], {%1, %2};"
                         :: "l"(&g_agg[(size_t)rn0 * 64 + col]), "f"(m00), "f"(m01) : "memory");
            asm volatile("red.global.add.v2.f32 [%0], {%1, %2};"
                         :: "l"(&g_agg[(size_t)rn1 * 64 + col]), "f"(m10), "f"(m11) : "memory");
            A3H[r0 * RSTR + nt * 4 + q]       = pack_bf16x2(m00, m01);
            A3H[(r0 + 8) * RSTR + nt * 4 + q] = pack_bf16x2(m10, m11);
        }
        __syncwarp();

        // ---- GEMM3: [16x64] = A3 (1-term bf16) x Wc1^T ----
        #pragma unroll
        for (int nt = 0; nt < 8; nt++)
            acc[nt][0] = acc[nt][1] = acc[nt][2] = acc[nt][3] = 0.f;
        #pragma unroll
        for (int ks = 0; ks < 4; ks++) {
            int abase = r0 * RSTR + ks * 8 + q;
            uint32_t a0 = A3H[abase],     a1 = A3H[abase + 8 * RSTR];
            uint32_t a2 = A3H[abase + 4], a3 = A3H[abase + 8 * RSTR + 4];
            #pragma unroll
            for (int nt = 0; nt < 8; nt++) {
                int bw = (nt * 8 + r0) * RSTR + ks * 8 + q;
                mma_bf16(acc[nt], a0, a1, a2, a3, smw[WCH_OFF + bw], smw[WCH_OFF + bw + 4]);
            }
        }

        // ---- epilogue3: c = silu(+bc1)@Wc2; coord atomics ----
        float s0 = 0.f, s1 = 0.f;
        #pragma unroll
        for (int nt = 0; nt < 8; nt++) {
            int col = nt * 8 + 2 * q;
            s0 += silu(acc[nt][0] + bc1s[col]) * wc2s[col]
                + silu(acc[nt][1] + bc1s[col + 1]) * wc2s[col + 1];
            s1 += silu(acc[nt][2] + bc1s[col]) * wc2s[col]
                + silu(acc[nt][3] + bc1s[col + 1]) * wc2s[col + 1];
        }
        s0 += __shfl_xor_sync(0xffffffffu, s0, 1);
        s0 += __shfl_xor_sync(0xffffffffu, s0, 2);
        s1 += __shfl_xor_sync(0xffffffffu, s1, 1);
        s1 += __shfl_xor_sync(0xffffffffu, s1, 2);
        if (q == 0) {
            float cc0 = s0 * mk0;
            atomicAdd(&g_aggc[(size_t)rn0 * 3 + 0], sDX[r0] * cc0);
            atomicAdd(&g_aggc[(size_t)rn0 * 3 + 1], sDY[r0] * cc0);
            atomicAdd(&g_aggc[(size_t)rn0 * 3 + 2], sDZ[r0] * cc0);
            atomicAdd(&g_cnt[rn0], 1.0f);
            float cc1 = s1 * mk1;
            atomicAdd(&g_aggc[(size_t)rn1 * 3 + 0], sDX[r0 + 8] * cc1);
            atomicAdd(&g_aggc[(size_t)rn1 * 3 + 1], sDY[r0 + 8] * cc1);
            atomicAdd(&g_aggc[(size_t)rn1 * 3 + 2], sDZ[r0 + 8] * cc1);
            atomicAdd(&g_cnt[rn1], 1.0f);
        }
        __syncwarp();
    }
}

// ---------------- node kernel (proven) ----------------
__global__ void node_kernel(const float* __restrict__ h, const float* __restrict__ coord,
                            const float* __restrict__ Wn1, const float* __restrict__ bn1,
                            const float* __restrict__ Wn2, const float* __restrict__ bn2,
                            float* __restrict__ hout, float* __restrict__ cout)
{
    extern __shared__ float sm[];
    float* sW1 = sm;
    float* sW2 = sW1 + 128 * 64;
    float* sb1 = sW2 + 64 * 64;
    float* sb2 = sb1 + 64;
    float* xall = sb2 + 64;

    int tid = threadIdx.x;
    for (int i = tid; i < 128 * 64; i += blockDim.x) sW1[i] = Wn1[i];
    for (int i = tid; i < 64 * 64; i += blockDim.x) sW2[i] = Wn2[i];
    if (tid < 64) { sb1[tid] = bn1[tid]; sb2[tid] = bn2[tid]; }
    __syncthreads();

    int lane = tid & 31, warp = tid >> 5;
    float* x = xall + warp * 128;
    const float2* xv = (const float2*)x;
    const float2* W1 = (const float2*)sW1;
    const float2* W2 = (const float2*)sW2;

    int gw = blockIdx.x * (blockDim.x >> 5) + warp;
    int nw = gridDim.x * (blockDim.x >> 5);
    for (int n = gw; n < NN; n += nw) {
        x[lane]      = h[(size_t)n * 64 + lane];
        x[32 + lane] = h[(size_t)n * 64 + 32 + lane];
        x[64 + lane] = g_agg[(size_t)n * 64 + lane];
        x[96 + lane] = g_agg[(size_t)n * 64 + 32 + lane];
        __syncwarp();

        float a0 = sb1[2 * lane], a1 = sb1[2 * lane + 1];
        #pragma unroll 8
        for (int k = 0; k < 64; k++) {
            float2 xk = xv[k];
            float2 w0 = W1[(2 * k) * 32 + lane];
            float2 w1 = W1[(2 * k + 1) * 32 + lane];
            a0 += xk.x * w0.x + xk.y * w1.x;
            a1 += xk.x * w0.y + xk.y * w1.y;
        }
        a0 = silu(a0); a1 = silu(a1);
        __syncwarp();
        x[2 * lane] = a0; x[2 * lane + 1] = a1;
        __syncwarp();

        float b0 = sb2[2 * lane], b1v = sb2[2 * lane + 1];
        #pragma unroll 8
        for (int k = 0; k < 32; k++) {
            float2 xk = xv[k];
            float2 w0 = W2[(2 * k) * 32 + lane];
            float2 w1 = W2[(2 * k + 1) * 32 + lane];
            b0  += xk.x * w0.x + xk.y * w1.x;
            b1v += xk.x * w0.y + xk.y * w1.y;
        }
        ((float2*)hout)[n * 32 + lane] = make_float2(b0, b1v);

        if (lane < 3) {
            float cnt = g_cnt[n];
            cnt = cnt > 1.f ? cnt : 1.f;
            cout[n * 3 + lane] = coord[n * 3 + lane] + g_aggc[n * 3 + lane] / cnt;
        }
        __syncwarp();
    }
}

extern "C" void kernel_launch(void* const* d_in, const int* in_sizes, int n_in,
                              void* d_out, int out_size)
{
    const float* h     = (const float*)d_in[0];
    const float* coord = (const float*)d_in[1];
    const void*  ei    = d_in[2];
    const float* emask = (const float*)d_in[3];
    const float* We1 = (const float*)d_in[4];  const float* be1 = (const float*)d_in[5];
    const float* We2 = (const float*)d_in[6];  const float* be2 = (const float*)d_in[7];
    const float* Wn1 = (const float*)d_in[8];  const float* bn1 = (const float*)d_in[9];
    const float* Wn2 = (const float*)d_in[10]; const float* bn2 = (const float*)d_in[11];
    const float* Wc1 = (const float*)d_in[12]; const float* bc1 = (const float*)d_in[13];
    const float* Wc2 = (const float*)d_in[14];

    float* hout = (float*)d_out;
    float* cout = hout + (size_t)NN * 64;

    const int smemH = (8192 + 64 + 8 * 64) * 4;                      // 34816
    const int smemN = (128 * 64 + 64 * 64 + 128 + 8 * 128) * 4;      // 53760
    cudaFuncSetAttribute(edge_kernel, cudaFuncAttributeMaxDynamicSharedMemorySize, SM_EDGE_BYTES);
    cudaFuncSetAttribute(node_kernel, cudaFuncAttributeMaxDynamicSharedMemorySize, smemN);

    zero_kernel<<<2048, 256>>>((const int*)ei);
    hprep_kernel<<<2048, 256, smemH>>>(h, We1, be1);
    edge_kernel<<<148, 512, SM_EDGE_BYTES>>>(coord, ei, emask, We1, We2, be2, Wc1, bc1, Wc2);
    node_kernel<<<608, 256, smemN>>>(h, coord, Wn1, bn1, Wn2, bn2, hout, cout);
}